// round 16
// baseline (speedup 1.0000x reference)
#include <cuda_runtime.h>
#include <math.h>
#include <stdint.h>
#include <limits.h>

#define T_DIM   4096
#define V_DIM   4096
#define FW      5
#define B_DIM   64
#define S_DIM   512
#define NROWS   (B_DIM * S_DIM)      // 32768
#define VK      (V_DIM * FW)         // 20480
#define TT      512                  // t-tile size (42 MB slice: L2-resident)
#define NTILES  (T_DIM / TT)         // 8
#define RPB     16                   // rows per kF CTA
#define THR_EPS 2e-6f                // candidate window (R12-validated)

typedef unsigned long long u64;

// Transposed weights: W_T[v*5+k][t], contiguous in t. 335 MB.
__device__ float g_wt[(size_t)VK * T_DIM];

// Per (row, tile) partial: 32 bytes.
struct __align__(16) Part {
    float s;        // sum of e^l (fp32 pairwise + butterfly)
    float w;        // sum of l * e^l
    float m;        // tile max (exact)
    float v1;       // candidate 1 value (first by index in window)
    int   i1;       // candidate 1 t index (INT_MAX if none)
    float v2;       // candidate 2 value
    int   i2;       // candidate 2 t index (INT_MAX if none)
    int   pad;
};
__device__ Part g_part[(size_t)NROWS * NTILES];   // [row][tile], 8 MB

// packed f32x2 add: per-component IEEE RN, bitwise == two scalar FADDs
__device__ __forceinline__ void add2(u64& acc, u64 v) {
    asm("add.rn.f32x2 %0, %1, %2;" : "=l"(acc) : "l"(acc), "l"(v));
}
__device__ __forceinline__ float2 u2f(u64 v) {
    float2 f;
    asm("mov.b64 {%0, %1}, %2;" : "=f"(f.x), "=f"(f.y) : "l"(v));
    return f;
}
// streaming 16B load (evict-first in L1: W_T has zero L1 reuse)
__device__ __forceinline__ ulonglong2 ldcs2(const float* p) {
    ulonglong2 r;
    asm("ld.global.cs.v2.u64 {%0, %1}, [%2];"
        : "=l"(r.x), "=l"(r.y) : "l"(p));
    return r;
}
// order-preserving float<->u32 (for REDUX.MAX)
__device__ __forceinline__ unsigned ford(float f) {
    int b = __float_as_int(f);
    return (unsigned)(b ^ ((b >> 31) | 0x80000000));
}
__device__ __forceinline__ float funord(unsigned u) {
    int b = (u & 0x80000000u) ? (int)(u ^ 0x80000000u) : (int)~u;
    return __int_as_float(b);
}

// ---------------------------------------------------------------------------
// kT: register-transpose, no smem. Each thread: 4t x 8vk micro-tile
// (8x LDG.128 streaming, in-register transpose, 8x STG.128 streaming).
// Also zeroes the entropy accumulator (half 0, block 0) — runs before k3.
// ---------------------------------------------------------------------------
__global__ __launch_bounds__(256)
void k_transpose(const float* __restrict__ W, int vk_half, float* out) {
    if (vk_half == 0 && blockIdx.x == 0 && blockIdx.y == 0 && threadIdx.x == 0)
        out[2 * NROWS] = 0.0f;

    const int lane = threadIdx.x & 31;
    const int wrp  = threadIdx.x >> 5;           // 0..7
    const int g    = lane >> 2;                  // vk8 group 0..7
    const int u    = lane & 3;                   // t-quad 0..3

    const int t0  = blockIdx.x * 16 + 4 * u;
    const int vk0 = (vk_half * (VK / 1024) + blockIdx.y) * 512 + wrp * 64 + 8 * g;

    const float* p0 = W + (size_t)t0 * VK + vk0;
    float4 a0 = __ldcs((const float4*)(p0));
    float4 b0 = __ldcs((const float4*)(p0 + 4));
    float4 a1 = __ldcs((const float4*)(p0 + VK));
    float4 b1 = __ldcs((const float4*)(p0 + VK + 4));
    float4 a2 = __ldcs((const float4*)(p0 + 2 * VK));
    float4 b2 = __ldcs((const float4*)(p0 + 2 * VK + 4));
    float4 a3 = __ldcs((const float4*)(p0 + 3 * VK));
    float4 b3 = __ldcs((const float4*)(p0 + 3 * VK + 4));

    float* q = g_wt + (size_t)vk0 * T_DIM + t0;
    __stcs((float4*)(q),             make_float4(a0.x, a1.x, a2.x, a3.x));
    __stcs((float4*)(q + T_DIM),     make_float4(a0.y, a1.y, a2.y, a3.y));
    __stcs((float4*)(q + 2 * T_DIM), make_float4(a0.z, a1.z, a2.z, a3.z));
    __stcs((float4*)(q + 3 * T_DIM), make_float4(a0.w, a1.w, a2.w, a3.w));
    __stcs((float4*)(q + 4 * T_DIM), make_float4(b0.x, b1.x, b2.x, b3.x));
    __stcs((float4*)(q + 5 * T_DIM), make_float4(b0.y, b1.y, b2.y, b3.y));
    __stcs((float4*)(q + 6 * T_DIM), make_float4(b0.z, b1.z, b2.z, b3.z));
    __stcs((float4*)(q + 7 * T_DIM), make_float4(b0.w, b1.w, b2.w, b3.w));
}

// ---------------------------------------------------------------------------
// kF: fused logits + per-tile softmax partials. Hot path carries only sums
// and chunk maxima; tie candidates extracted from REGISTER-resident logits.
// (512, 4): 32-reg target to reach 64 warps/SM — cold-path spills are fine.
// Accumulation order is the reference's exact fp32 order per component.
// ---------------------------------------------------------------------------
__global__ __launch_bounds__(512, 4)
void k_fused(const float* __restrict__ b, const int* __restrict__ x) {
    __shared__ int tokvk[RPB + 4];

    const int bid  = blockIdx.x;
    const int tile = bid / (NROWS / RPB);
    const int rblk = bid % (NROWS / RPB);
    const int bi   = rblk / (S_DIM / RPB);
    const int s0   = (rblk % (S_DIM / RPB)) * RPB;
    const int t0   = tile * TT;

    if (threadIdx.x < RPB + 4) {
        int p = s0 - 2 + threadIdx.x;
        int v = (p >= 0 && p < S_DIM) ? x[bi * S_DIM + p] : 0;
        tokvk[threadIdx.x] = v * 5;
    }
    __syncthreads();

    const int wrp  = threadIdx.x >> 5;
    const int lane = threadIdx.x & 31;
    const int s    = s0 + wrp;

    int woff[FW];
    #pragma unroll
    for (int k = 0; k < FW; k++) {
        int p = s - 2 + k;
        woff[k] = (p >= 0 && p < S_DIM) ? (tokvk[wrp + k] + k) : -1;
    }

    // ---- logits: 4 chunks of 4 floats as 2 packed f32x2 each ----
    u64 acc[8];
    #pragma unroll
    for (int jj = 0; jj < 4; jj++) {
        ulonglong2 bb = __ldg((const ulonglong2*)(b + t0 + 128 * jj + lane * 4));
        acc[2 * jj]     = bb.x;
        acc[2 * jj + 1] = bb.y;
    }
    #pragma unroll
    for (int k = 0; k < FW; k++) {
        if (woff[k] >= 0) {
            const float* Wr = g_wt + (size_t)woff[k] * T_DIM + t0 + lane * 4;
            #pragma unroll
            for (int jj = 0; jj < 4; jj++) {
                ulonglong2 ww = ldcs2(Wr + 128 * jj);
                add2(acc[2 * jj],     ww.x);
                add2(acc[2 * jj + 1], ww.y);
            }
        }
    }

    // ---- stats: sums + chunk maxima only (no per-element index ops) ----
    float csum[4], cm[4];
    float wsum0 = 0.0f, wsum1 = 0.0f;
    #pragma unroll
    for (int jj = 0; jj < 4; jj++) {
        float2 lo = u2f(acc[2 * jj]);
        float2 hi = u2f(acc[2 * jj + 1]);
        float e0 = __expf(lo.x);
        float e1 = __expf(lo.y);
        float e2 = __expf(hi.x);
        float e3 = __expf(hi.y);
        csum[jj] = (e0 + e1) + (e2 + e3);
        wsum0 = fmaf(lo.x, e0, wsum0);
        wsum1 = fmaf(lo.y, e1, wsum1);
        wsum0 = fmaf(hi.x, e2, wsum0);
        wsum1 = fmaf(hi.y, e3, wsum1);
        cm[jj] = fmaxf(fmaxf(lo.x, lo.y), fmaxf(hi.x, hi.y));
    }
    float vmax = fmaxf(fmaxf(cm[0], cm[1]), fmaxf(cm[2], cm[3]));
    float ssum = (csum[0] + csum[1]) + (csum[2] + csum[3]);
    float wsum = wsum0 + wsum1;

    // ---- butterfly sums + HW max reduce ----
    #pragma unroll
    for (int off = 16; off > 0; off >>= 1) {
        ssum += __shfl_xor_sync(0xffffffffu, ssum, off);
        wsum += __shfl_xor_sync(0xffffffffu, wsum, off);
    }
    const float mt  = funord(__reduce_max_sync(0xffffffffu, ford(vmax)));
    const float thr = mt - THR_EPS;

    // ---- candidate extraction from REGISTERS (typically 1 lane active) ----
    float v_c1 = -INFINITY, v_c2 = -INFINITY;
    int   i_c1 = INT_MAX,   i_c2 = INT_MAX;
    if (vmax >= thr) {
        #pragma unroll
        for (int jj = 0; jj < 4; jj++) {
            if (cm[jj] >= thr) {
                float2 lo = u2f(acc[2 * jj]);
                float2 hi = u2f(acc[2 * jj + 1]);
                float vv[4] = {lo.x, lo.y, hi.x, hi.y};
                #pragma unroll
                for (int q = 0; q < 4; q++) {
                    float l = vv[q];
                    if (l >= thr) {
                        int t = t0 + 128 * jj + lane * 4 + q;
                        if (i_c1 == INT_MAX)      { v_c1 = l; i_c1 = t; }
                        else if (i_c2 == INT_MAX) { v_c2 = l; i_c2 = t; }
                    }
                }
            }
        }
    }

    // ---- merge candidates across lanes (popc==1 is the common case) ----
    unsigned have = __ballot_sync(0xffffffffu, i_c1 != INT_MAX);
    int   j1, j2; float w1, w2;
    if (__popc(have) == 1) {
        int src = __ffs(have) - 1;
        j1 = __shfl_sync(0xffffffffu, i_c1, src);
        w1 = __shfl_sync(0xffffffffu, v_c1, src);
        j2 = __shfl_sync(0xffffffffu, i_c2, src);
        w2 = __shfl_sync(0xffffffffu, v_c2, src);
    } else {
        // rare: two smallest-by-index among all lanes' (c1, c2)
        u64 k1 = ((u64)(unsigned)i_c1 << 32) | (unsigned)__float_as_uint(v_c1);
        u64 k2 = ((u64)(unsigned)i_c2 << 32) | (unsigned)__float_as_uint(v_c2);
        #pragma unroll
        for (int off = 16; off > 0; off >>= 1) {
            u64 o1 = __shfl_xor_sync(0xffffffffu, k1, off);
            u64 o2 = __shfl_xor_sync(0xffffffffu, k2, off);
            u64 n1  = (k1 < o1) ? k1 : o1;
            u64 hi1 = (k1 < o1) ? o1 : k1;
            u64 lo2 = (k2 < o2) ? k2 : o2;
            k2 = (hi1 < lo2) ? hi1 : lo2;
            k1 = n1;
        }
        j1 = (int)(k1 >> 32); w1 = __uint_as_float((unsigned)k1);
        j2 = (int)(k2 >> 32); w2 = __uint_as_float((unsigned)k2);
    }

    if (lane == 0) {
        int row = bi * S_DIM + s;
        Part p;
        p.s = ssum; p.w = wsum; p.m = mt;
        p.v1 = w1; p.i1 = j1; p.v2 = w2; p.i2 = j2; p.pad = 0;
        g_part[(size_t)row * NTILES + tile] = p;
    }
}

// ---------------------------------------------------------------------------
// k3: merge NTILES=8 partials per row -> outputs. All fp32.
// CTA = 256 threads = 8 warps = 8 rows; lane = tile (8 active).
// ---------------------------------------------------------------------------
__global__ __launch_bounds__(256)
void k3_final(float* __restrict__ out) {
    __shared__ float hacc;
    const int wrp  = threadIdx.x >> 5;
    const int lane = threadIdx.x & 31;
    const int row  = blockIdx.x * 8 + wrp;

    if (threadIdx.x == 0) hacc = 0.0f;
    __syncthreads();

    float s = 0.0f, w = 0.0f, m = -INFINITY;
    float w1 = -INFINITY, w2 = -INFINITY;
    int   j1 = INT_MAX,   j2 = INT_MAX;
    if (lane < NTILES) {
        Part p = g_part[(size_t)row * NTILES + lane];
        s = p.s; w = p.w; m = p.m;
        w1 = p.v1; j1 = p.i1; w2 = p.v2; j2 = p.i2;
    }

    // butterfly: all lanes get row totals (identical bitwise)
    #pragma unroll
    for (int off = 16; off > 0; off >>= 1) {
        s += __shfl_xor_sync(0xffffffffu, s, off);
        w += __shfl_xor_sync(0xffffffffu, w, off);
        m = fmaxf(m, __shfl_xor_sync(0xffffffffu, m, off));
    }

    float ls0   = __logf(s);           // ln(sum e^l), fp32 grid point
    float lse_f = ls0 - m;             // ~ ref's log(sum e^{l-m})
    float key0  = 0.0f - lse_f;        // rounded key of the max

    // tie-aware argmax: first index whose rounded key equals the max key
    int cand = INT_MAX;
    if (j1 != INT_MAX && ((w1 - m) - lse_f) == key0) cand = j1;
    if (j2 != INT_MAX && ((w2 - m) - lse_f) == key0) cand = min(cand, j2);
    #pragma unroll
    for (int off = 16; off > 0; off >>= 1)
        cand = min(cand, __shfl_xor_sync(0xffffffffu, cand, off));

    if (lane == 0) {
        out[row]         = (float)cand;
        out[NROWS + row] = -lse_f;
        float H = ls0 - w / s;
        atomicAdd(&hacc, H * (1.0f / ((float)NROWS * (float)T_DIM)));
    }
    __syncthreads();
    if (threadIdx.x == 0) atomicAdd(out + 2 * NROWS, hacc);
}

// ---------------------------------------------------------------------------
extern "C" void kernel_launch(void* const* d_in, const int* in_sizes, int n_in,
                              void* d_out, int out_size) {
    const float* W = nullptr;
    const float* b = nullptr;
    const int*   x = nullptr;
    for (int i = 0; i < n_in; i++) {
        if (in_sizes[i] == T_DIM * V_DIM * FW) W = (const float*)d_in[i];
        else if (in_sizes[i] == T_DIM)         b = (const float*)d_in[i];
        else if (in_sizes[i] == NROWS)         x = (const int*)d_in[i];
    }
    float* out = (float*)d_out;

    // 4 launches: kT (zeroes entropy slot too), kT, kF, k3.
    const dim3 kt_grid(T_DIM / 16, VK / 1024);   // 256 x 20 per half
    k_transpose<<<kt_grid, 256>>>(W, 0, out);
    k_transpose<<<kt_grid, 256>>>(W, 1, out);
    k_fused<<<NTILES * (NROWS / RPB), 512>>>(b, x);
    k3_final<<<NROWS / 8, 256>>>(out);
}

// round 17
// speedup vs baseline: 1.0224x; 1.0224x over previous
#include <cuda_runtime.h>
#include <math.h>
#include <stdint.h>
#include <limits.h>

#define T_DIM   4096
#define V_DIM   4096
#define FW      5
#define B_DIM   64
#define S_DIM   512
#define NROWS   (B_DIM * S_DIM)      // 32768
#define VK      (V_DIM * FW)         // 20480
#define TT      512                  // t-tile size (42 MB slice: L2-resident)
#define NTILES  (T_DIM / TT)         // 8
#define RPB     16                   // rows per kF CTA
#define THR_EPS 2e-6f                // candidate window (R12-validated)

typedef unsigned long long u64;

// Transposed weights: W_T[v*5+k][t], contiguous in t. 335 MB.
__device__ float g_wt[(size_t)VK * T_DIM];

// Per (row, tile) partial: 32 bytes.
struct __align__(16) Part {
    float s;        // sum of e^l (fp32 pairwise + butterfly)
    float w;        // sum of l * e^l
    float m;        // tile max (exact)
    float v1;       // candidate 1 value (first by index in window)
    int   i1;       // candidate 1 t index (INT_MAX if none)
    float v2;       // candidate 2 value
    int   i2;       // candidate 2 t index (INT_MAX if none)
    int   pad;
};
__device__ Part g_part[(size_t)NROWS * NTILES];   // [row][tile], 8 MB

// packed f32x2 add: per-component IEEE RN, bitwise == two scalar FADDs
__device__ __forceinline__ void add2(u64& acc, u64 v) {
    asm("add.rn.f32x2 %0, %1, %2;" : "=l"(acc) : "l"(acc), "l"(v));
}
__device__ __forceinline__ float2 u2f(u64 v) {
    float2 f;
    asm("mov.b64 {%0, %1}, %2;" : "=f"(f.x), "=f"(f.y) : "l"(v));
    return f;
}
// streaming 16B load (evict-first in L1: W_T has zero L1 reuse)
__device__ __forceinline__ ulonglong2 ldcs2(const float* p) {
    ulonglong2 r;
    asm("ld.global.cs.v2.u64 {%0, %1}, [%2];"
        : "=l"(r.x), "=l"(r.y) : "l"(p));
    return r;
}
// order-preserving float<->u32 (for REDUX.MAX)
__device__ __forceinline__ unsigned ford(float f) {
    int b = __float_as_int(f);
    return (unsigned)(b ^ ((b >> 31) | 0x80000000));
}
__device__ __forceinline__ float funord(unsigned u) {
    int b = (u & 0x80000000u) ? (int)(u ^ 0x80000000u) : (int)~u;
    return __int_as_float(b);
}

// ---------------------------------------------------------------------------
// kT: register-transpose, no smem. Each thread: 4t x 8vk micro-tile
// (8x LDG.128 streaming, in-register transpose, 8x STG.128 streaming).
// Also zeroes the entropy accumulator (half 0, block 0) — runs before k3.
// At the DRAM wall: ~6.8 TB/s on 670 GB r+w.
// ---------------------------------------------------------------------------
__global__ __launch_bounds__(256)
void k_transpose(const float* __restrict__ W, int vk_half, float* out) {
    if (vk_half == 0 && blockIdx.x == 0 && blockIdx.y == 0 && threadIdx.x == 0)
        out[2 * NROWS] = 0.0f;

    const int lane = threadIdx.x & 31;
    const int wrp  = threadIdx.x >> 5;           // 0..7
    const int g    = lane >> 2;                  // vk8 group 0..7
    const int u    = lane & 3;                   // t-quad 0..3

    const int t0  = blockIdx.x * 16 + 4 * u;
    const int vk0 = (vk_half * (VK / 1024) + blockIdx.y) * 512 + wrp * 64 + 8 * g;

    const float* p0 = W + (size_t)t0 * VK + vk0;
    float4 a0 = __ldcs((const float4*)(p0));
    float4 b0 = __ldcs((const float4*)(p0 + 4));
    float4 a1 = __ldcs((const float4*)(p0 + VK));
    float4 b1 = __ldcs((const float4*)(p0 + VK + 4));
    float4 a2 = __ldcs((const float4*)(p0 + 2 * VK));
    float4 b2 = __ldcs((const float4*)(p0 + 2 * VK + 4));
    float4 a3 = __ldcs((const float4*)(p0 + 3 * VK));
    float4 b3 = __ldcs((const float4*)(p0 + 3 * VK + 4));

    float* q = g_wt + (size_t)vk0 * T_DIM + t0;
    __stcs((float4*)(q),             make_float4(a0.x, a1.x, a2.x, a3.x));
    __stcs((float4*)(q + T_DIM),     make_float4(a0.y, a1.y, a2.y, a3.y));
    __stcs((float4*)(q + 2 * T_DIM), make_float4(a0.z, a1.z, a2.z, a3.z));
    __stcs((float4*)(q + 3 * T_DIM), make_float4(a0.w, a1.w, a2.w, a3.w));
    __stcs((float4*)(q + 4 * T_DIM), make_float4(b0.x, b1.x, b2.x, b3.x));
    __stcs((float4*)(q + 5 * T_DIM), make_float4(b0.y, b1.y, b2.y, b3.y));
    __stcs((float4*)(q + 6 * T_DIM), make_float4(b0.z, b1.z, b2.z, b3.z));
    __stcs((float4*)(q + 7 * T_DIM), make_float4(b0.w, b1.w, b2.w, b3.w));
}

// ---------------------------------------------------------------------------
// kF: fused logits + per-tile softmax partials. Hot path carries only sums
// and chunk maxima; tie candidates extracted from REGISTER-resident logits.
// (512, 3): ptxas's preferred 40-reg allocation — measured 176us (R14/R15).
// Accumulation order is the reference's exact fp32 order per component
// (b + k0 + k1 + k2 + k3 + k4).
// ---------------------------------------------------------------------------
__global__ __launch_bounds__(512, 3)
void k_fused(const float* __restrict__ b, const int* __restrict__ x) {
    __shared__ int tokvk[RPB + 4];

    const int bid  = blockIdx.x;
    const int tile = bid / (NROWS / RPB);
    const int rblk = bid % (NROWS / RPB);
    const int bi   = rblk / (S_DIM / RPB);
    const int s0   = (rblk % (S_DIM / RPB)) * RPB;
    const int t0   = tile * TT;

    if (threadIdx.x < RPB + 4) {
        int p = s0 - 2 + threadIdx.x;
        int v = (p >= 0 && p < S_DIM) ? x[bi * S_DIM + p] : 0;
        tokvk[threadIdx.x] = v * 5;
    }
    __syncthreads();

    const int wrp  = threadIdx.x >> 5;
    const int lane = threadIdx.x & 31;
    const int s    = s0 + wrp;

    int woff[FW];
    #pragma unroll
    for (int k = 0; k < FW; k++) {
        int p = s - 2 + k;
        woff[k] = (p >= 0 && p < S_DIM) ? (tokvk[wrp + k] + k) : -1;
    }

    // ---- logits: 4 chunks of 4 floats as 2 packed f32x2 each ----
    u64 acc[8];
    #pragma unroll
    for (int jj = 0; jj < 4; jj++) {
        ulonglong2 bb = __ldg((const ulonglong2*)(b + t0 + 128 * jj + lane * 4));
        acc[2 * jj]     = bb.x;
        acc[2 * jj + 1] = bb.y;
    }
    #pragma unroll
    for (int k = 0; k < FW; k++) {
        if (woff[k] >= 0) {
            const float* Wr = g_wt + (size_t)woff[k] * T_DIM + t0 + lane * 4;
            #pragma unroll
            for (int jj = 0; jj < 4; jj++) {
                ulonglong2 ww = ldcs2(Wr + 128 * jj);
                add2(acc[2 * jj],     ww.x);
                add2(acc[2 * jj + 1], ww.y);
            }
        }
    }

    // ---- stats: sums + chunk maxima only (no per-element index ops) ----
    float csum[4], cm[4];
    float wsum0 = 0.0f, wsum1 = 0.0f;
    #pragma unroll
    for (int jj = 0; jj < 4; jj++) {
        float2 lo = u2f(acc[2 * jj]);
        float2 hi = u2f(acc[2 * jj + 1]);
        float e0 = __expf(lo.x);
        float e1 = __expf(lo.y);
        float e2 = __expf(hi.x);
        float e3 = __expf(hi.y);
        csum[jj] = (e0 + e1) + (e2 + e3);
        wsum0 = fmaf(lo.x, e0, wsum0);
        wsum1 = fmaf(lo.y, e1, wsum1);
        wsum0 = fmaf(hi.x, e2, wsum0);
        wsum1 = fmaf(hi.y, e3, wsum1);
        cm[jj] = fmaxf(fmaxf(lo.x, lo.y), fmaxf(hi.x, hi.y));
    }
    float vmax = fmaxf(fmaxf(cm[0], cm[1]), fmaxf(cm[2], cm[3]));
    float ssum = (csum[0] + csum[1]) + (csum[2] + csum[3]);
    float wsum = wsum0 + wsum1;

    // ---- butterfly sums + HW max reduce ----
    #pragma unroll
    for (int off = 16; off > 0; off >>= 1) {
        ssum += __shfl_xor_sync(0xffffffffu, ssum, off);
        wsum += __shfl_xor_sync(0xffffffffu, wsum, off);
    }
    const float mt  = funord(__reduce_max_sync(0xffffffffu, ford(vmax)));
    const float thr = mt - THR_EPS;

    // ---- candidate extraction from REGISTERS (typically 1 lane active) ----
    float v_c1 = -INFINITY, v_c2 = -INFINITY;
    int   i_c1 = INT_MAX,   i_c2 = INT_MAX;
    if (vmax >= thr) {
        #pragma unroll
        for (int jj = 0; jj < 4; jj++) {
            if (cm[jj] >= thr) {
                float2 lo = u2f(acc[2 * jj]);
                float2 hi = u2f(acc[2 * jj + 1]);
                float vv[4] = {lo.x, lo.y, hi.x, hi.y};
                #pragma unroll
                for (int q = 0; q < 4; q++) {
                    float l = vv[q];
                    if (l >= thr) {
                        int t = t0 + 128 * jj + lane * 4 + q;
                        if (i_c1 == INT_MAX)      { v_c1 = l; i_c1 = t; }
                        else if (i_c2 == INT_MAX) { v_c2 = l; i_c2 = t; }
                    }
                }
            }
        }
    }

    // ---- merge candidates across lanes (popc==1 is the common case) ----
    unsigned have = __ballot_sync(0xffffffffu, i_c1 != INT_MAX);
    int   j1, j2; float w1, w2;
    if (__popc(have) == 1) {
        int src = __ffs(have) - 1;
        j1 = __shfl_sync(0xffffffffu, i_c1, src);
        w1 = __shfl_sync(0xffffffffu, v_c1, src);
        j2 = __shfl_sync(0xffffffffu, i_c2, src);
        w2 = __shfl_sync(0xffffffffu, v_c2, src);
    } else {
        // rare: two smallest-by-index among all lanes' (c1, c2)
        u64 k1 = ((u64)(unsigned)i_c1 << 32) | (unsigned)__float_as_uint(v_c1);
        u64 k2 = ((u64)(unsigned)i_c2 << 32) | (unsigned)__float_as_uint(v_c2);
        #pragma unroll
        for (int off = 16; off > 0; off >>= 1) {
            u64 o1 = __shfl_xor_sync(0xffffffffu, k1, off);
            u64 o2 = __shfl_xor_sync(0xffffffffu, k2, off);
            u64 n1  = (k1 < o1) ? k1 : o1;
            u64 hi1 = (k1 < o1) ? o1 : k1;
            u64 lo2 = (k2 < o2) ? k2 : o2;
            k2 = (hi1 < lo2) ? hi1 : lo2;
            k1 = n1;
        }
        j1 = (int)(k1 >> 32); w1 = __uint_as_float((unsigned)k1);
        j2 = (int)(k2 >> 32); w2 = __uint_as_float((unsigned)k2);
    }

    if (lane == 0) {
        int row = bi * S_DIM + s;
        Part p;
        p.s = ssum; p.w = wsum; p.m = mt;
        p.v1 = w1; p.i1 = j1; p.v2 = w2; p.i2 = j2; p.pad = 0;
        g_part[(size_t)row * NTILES + tile] = p;
    }
}

// ---------------------------------------------------------------------------
// k3: merge NTILES=8 partials per row -> outputs. All fp32.
// CTA = 256 threads = 8 warps = 8 rows; lane = tile (8 active).
// ---------------------------------------------------------------------------
__global__ __launch_bounds__(256)
void k3_final(float* __restrict__ out) {
    __shared__ float hacc;
    const int wrp  = threadIdx.x >> 5;
    const int lane = threadIdx.x & 31;
    const int row  = blockIdx.x * 8 + wrp;

    if (threadIdx.x == 0) hacc = 0.0f;
    __syncthreads();

    float s = 0.0f, w = 0.0f, m = -INFINITY;
    float w1 = -INFINITY, w2 = -INFINITY;
    int   j1 = INT_MAX,   j2 = INT_MAX;
    if (lane < NTILES) {
        Part p = g_part[(size_t)row * NTILES + lane];
        s = p.s; w = p.w; m = p.m;
        w1 = p.v1; j1 = p.i1; w2 = p.v2; j2 = p.i2;
    }

    // butterfly: all lanes get row totals (identical bitwise)
    #pragma unroll
    for (int off = 16; off > 0; off >>= 1) {
        s += __shfl_xor_sync(0xffffffffu, s, off);
        w += __shfl_xor_sync(0xffffffffu, w, off);
        m = fmaxf(m, __shfl_xor_sync(0xffffffffu, m, off));
    }

    float ls0   = __logf(s);           // ln(sum e^l), fp32 grid point
    float lse_f = ls0 - m;             // ~ ref's log(sum e^{l-m})
    float key0  = 0.0f - lse_f;        // rounded key of the max

    // tie-aware argmax: first index whose rounded key equals the max key
    int cand = INT_MAX;
    if (j1 != INT_MAX && ((w1 - m) - lse_f) == key0) cand = j1;
    if (j2 != INT_MAX && ((w2 - m) - lse_f) == key0) cand = min(cand, j2);
    #pragma unroll
    for (int off = 16; off > 0; off >>= 1)
        cand = min(cand, __shfl_xor_sync(0xffffffffu, cand, off));

    if (lane == 0) {
        out[row]         = (float)cand;
        out[NROWS + row] = -lse_f;
        float H = ls0 - w / s;
        atomicAdd(&hacc, H * (1.0f / ((float)NROWS * (float)T_DIM)));
    }
    __syncthreads();
    if (threadIdx.x == 0) atomicAdd(out + 2 * NROWS, hacc);
}

// ---------------------------------------------------------------------------
extern "C" void kernel_launch(void* const* d_in, const int* in_sizes, int n_in,
                              void* d_out, int out_size) {
    const float* W = nullptr;
    const float* b = nullptr;
    const int*   x = nullptr;
    for (int i = 0; i < n_in; i++) {
        if (in_sizes[i] == T_DIM * V_DIM * FW) W = (const float*)d_in[i];
        else if (in_sizes[i] == T_DIM)         b = (const float*)d_in[i];
        else if (in_sizes[i] == NROWS)         x = (const int*)d_in[i];
    }
    float* out = (float*)d_out;

    // 4 launches: kT (also zeroes entropy slot), kT, kF, k3.
    const dim3 kt_grid(T_DIM / 16, VK / 1024);   // 256 x 20 per half
    k_transpose<<<kt_grid, 256>>>(W, 0, out);
    k_transpose<<<kt_grid, 256>>>(W, 1, out);
    k_fused<<<NTILES * (NROWS / RPB), 512>>>(b, x);
    k3_final<<<NROWS / 8, 256>>>(out);
}